// round 6
// baseline (speedup 1.0000x reference)
#include <cuda_runtime.h>

#define BATCH 8
#define SEQ   4096
#define EMB   512
#define HD    64

// scratch for q, k, v  (8 MB each — __device__ globals, allocation-free)
__device__ float g_q[BATCH * SEQ * HD];
__device__ float g_k[BATCH * SEQ * HD];
__device__ float g_v[BATCH * SEQ * HD];

// ---------------------------------------------------------------------------
// Fused QKV projection: x[32768, 512] @ {Wq,Wk,Wv}[512, 64] -> g_q/g_k/g_v
// Block: 64 rows x all 192 output cols. 256 threads, thread tile 4 rows x
// (4 cols per matrix). x is read from DRAM exactly once.
// ---------------------------------------------------------------------------
__global__ __launch_bounds__(256) void qkv_proj(
    const float* __restrict__ x,
    const float* __restrict__ Wq,
    const float* __restrict__ Wk,
    const float* __restrict__ Wv)
{
    __shared__ float As[64 * 32];        // A tile, stride 32
    __shared__ float Ws[3 * 32 * 64];    // 3 weight tiles [m][k][c]

    const int tid = threadIdx.x;
    const int ty = tid >> 4, tx = tid & 15;
    const long row0 = (long)blockIdx.x * 64;

    float acc[3][4][4];
#pragma unroll
    for (int m = 0; m < 3; m++)
#pragma unroll
        for (int i = 0; i < 4; i++)
#pragma unroll
            for (int j = 0; j < 4; j++) acc[m][i][j] = 0.f;

    for (int kb = 0; kb < EMB; kb += 32) {
        // load A tile: 64 x 32 = 512 float4
#pragma unroll
        for (int l = 0; l < 2; l++) {
            int idx = tid + l * 256;
            int r = idx >> 3, kg = idx & 7;
            *(float4*)&As[r * 32 + kg * 4] =
                *(const float4*)&x[(row0 + r) * EMB + kb + kg * 4];
        }
        // load W tiles: 3 * 32 * 64 floats = 1536 float4
#pragma unroll
        for (int l = 0; l < 6; l++) {
            int idx = tid + l * 256;
            int m = idx >> 9;
            int rem = idx & 511;
            int r = rem >> 4, c4 = rem & 15;
            const float* w = (m == 0) ? Wq : ((m == 1) ? Wk : Wv);
            *(float4*)&Ws[(m * 32 + r) * 64 + c4 * 4] =
                *(const float4*)&w[(kb + r) * HD + c4 * 4];
        }
        __syncthreads();

#pragma unroll
        for (int k = 0; k < 32; k++) {
            float a[4];
#pragma unroll
            for (int i = 0; i < 4; i++) a[i] = As[(4 * ty + i) * 32 + k];
#pragma unroll
            for (int m = 0; m < 3; m++) {
                float4 w = *(float4*)&Ws[(m * 32 + k) * 64 + tx * 4];
#pragma unroll
                for (int i = 0; i < 4; i++) {
                    acc[m][i][0] = fmaf(a[i], w.x, acc[m][i][0]);
                    acc[m][i][1] = fmaf(a[i], w.y, acc[m][i][1]);
                    acc[m][i][2] = fmaf(a[i], w.z, acc[m][i][2]);
                    acc[m][i][3] = fmaf(a[i], w.w, acc[m][i][3]);
                }
            }
        }
        __syncthreads();
    }

#pragma unroll
    for (int i = 0; i < 4; i++) {
        long r = row0 + 4 * ty + i;
        *(float4*)&g_q[r * HD + tx * 4] =
            make_float4(acc[0][i][0], acc[0][i][1], acc[0][i][2], acc[0][i][3]);
        *(float4*)&g_k[r * HD + tx * 4] =
            make_float4(acc[1][i][0], acc[1][i][1], acc[1][i][2], acc[1][i][3]);
        *(float4*)&g_v[r * HD + tx * 4] =
            make_float4(acc[2][i][0], acc[2][i][1], acc[2][i][2], acc[2][i][3]);
    }
}

// ---------------------------------------------------------------------------
// Flash-attention (fp32, causal). Each block handles q-tile pair {bx, 63-bx}
// for one batch -> exactly 65 key-tile iterations per block (perfect balance).
// Thread (ty,tx): S rows 4ty..4ty+3, S cols {tx, tx+16, tx+32, tx+48},
// O cols tx*4..tx*4+3. Softmax tracked in log2 domain.
// ---------------------------------------------------------------------------
#define QS_STRIDE 65   // padded: conflict-free scalar reads
#define KS_STRIDE 65
#define PS_STRIDE 68   // padded, float4-aligned

__global__ __launch_bounds__(256) void attn(float* __restrict__ out)
{
    extern __shared__ float sm[];
    float* Qs = sm;                       // 64*65
    float* Ks = Qs + 64 * QS_STRIDE;      // 64*65
    float* Vs = Ks + 64 * KS_STRIDE;      // 64*64 (natural)
    float* Ps = Vs + 64 * HD;             // 64*68

    const int tid = threadIdx.x;
    const int ty = tid >> 4, tx = tid & 15;
    const int b = blockIdx.y;
    const float cfac = 0.06379864817f;    // 512^-0.5 * log2(e)

#pragma unroll 1
    for (int half = 0; half < 2; half++) {
        const int qi = half ? (63 - (int)blockIdx.x) : (int)blockIdx.x;
        const long qbase = ((long)b * SEQ + (long)qi * 64) * HD;

        // load Q tile into padded smem
#pragma unroll
        for (int l = 0; l < 4; l++) {
            int idx = tid + l * 256;              // 1024 float4
            int r = idx >> 4, h4 = (idx & 15) * 4;
            float4 v = *(const float4*)&g_q[qbase + r * HD + h4];
            Qs[r * QS_STRIDE + h4 + 0] = v.x;
            Qs[r * QS_STRIDE + h4 + 1] = v.y;
            Qs[r * QS_STRIDE + h4 + 2] = v.z;
            Qs[r * QS_STRIDE + h4 + 3] = v.w;
        }

        float mrow[4], lrow[4], o[4][4];
#pragma unroll
        for (int i = 0; i < 4; i++) {
            mrow[i] = -3.0e38f;
            lrow[i] = 0.f;
#pragma unroll
            for (int j = 0; j < 4; j++) o[i][j] = 0.f;
        }

        for (int kt = 0; kt <= qi; kt++) {
            __syncthreads();   // prior iter's P*V reads of Vs/Ps are done
            const long kbase = ((long)b * SEQ + (long)kt * 64) * HD;
#pragma unroll
            for (int l = 0; l < 4; l++) {
                int idx = tid + l * 256;
                int c = idx >> 4, h4 = (idx & 15) * 4;
                float4 kv = *(const float4*)&g_k[kbase + c * HD + h4];
                Ks[c * KS_STRIDE + h4 + 0] = kv.x;
                Ks[c * KS_STRIDE + h4 + 1] = kv.y;
                Ks[c * KS_STRIDE + h4 + 2] = kv.z;
                Ks[c * KS_STRIDE + h4 + 3] = kv.w;
                *(float4*)&Vs[c * HD + h4] =
                    *(const float4*)&g_v[kbase + c * HD + h4];
            }
            __syncthreads();

            // ---- S = Q K^T ----
            float s[4][4];
#pragma unroll
            for (int i = 0; i < 4; i++)
#pragma unroll
                for (int j = 0; j < 4; j++) s[i][j] = 0.f;

            const float* qb  = &Qs[(4 * ty) * QS_STRIDE];
            const float* kbp = &Ks[tx * KS_STRIDE];
#pragma unroll 8
            for (int h = 0; h < HD; h++) {
                float q0 = qb[0 * QS_STRIDE + h];
                float q1 = qb[1 * QS_STRIDE + h];
                float q2 = qb[2 * QS_STRIDE + h];
                float q3 = qb[3 * QS_STRIDE + h];
                float k0 = kbp[ 0 * KS_STRIDE + h];
                float k1 = kbp[16 * KS_STRIDE + h];
                float k2 = kbp[32 * KS_STRIDE + h];
                float k3 = kbp[48 * KS_STRIDE + h];
                s[0][0] = fmaf(q0, k0, s[0][0]); s[0][1] = fmaf(q0, k1, s[0][1]);
                s[0][2] = fmaf(q0, k2, s[0][2]); s[0][3] = fmaf(q0, k3, s[0][3]);
                s[1][0] = fmaf(q1, k0, s[1][0]); s[1][1] = fmaf(q1, k1, s[1][1]);
                s[1][2] = fmaf(q1, k2, s[1][2]); s[1][3] = fmaf(q1, k3, s[1][3]);
                s[2][0] = fmaf(q2, k0, s[2][0]); s[2][1] = fmaf(q2, k1, s[2][1]);
                s[2][2] = fmaf(q2, k2, s[2][2]); s[2][3] = fmaf(q2, k3, s[2][3]);
                s[3][0] = fmaf(q3, k0, s[3][0]); s[3][1] = fmaf(q3, k1, s[3][1]);
                s[3][2] = fmaf(q3, k2, s[3][2]); s[3][3] = fmaf(q3, k3, s[3][3]);
            }

            // ---- scale + causal mask + online softmax (log2 domain) ----
            const bool diag = (kt == qi);
#pragma unroll
            for (int i = 0; i < 4; i++) {
                const int rloc = 4 * ty + i;
#pragma unroll
                for (int j = 0; j < 4; j++) {
                    float v = s[i][j] * cfac;
                    if (diag && (tx + 16 * j) > rloc) v = -1e30f;
                    s[i][j] = v;
                }
                float mx = fmaxf(fmaxf(s[i][0], s[i][1]), fmaxf(s[i][2], s[i][3]));
#pragma unroll
                for (int off = 8; off >= 1; off >>= 1)
                    mx = fmaxf(mx, __shfl_xor_sync(0xffffffffu, mx, off));
                const float mnew = fmaxf(mrow[i], mx);
                const float corr = exp2f(mrow[i] - mnew);
                float rs = 0.f;
#pragma unroll
                for (int j = 0; j < 4; j++) {
                    float p = exp2f(s[i][j] - mnew);
                    s[i][j] = p;
                    rs += p;
                }
#pragma unroll
                for (int off = 8; off >= 1; off >>= 1)
                    rs += __shfl_xor_sync(0xffffffffu, rs, off);
                lrow[i] = lrow[i] * corr + rs;
                mrow[i] = mnew;
#pragma unroll
                for (int j = 0; j < 4; j++) o[i][j] *= corr;
            }

            // ---- write P ----
#pragma unroll
            for (int i = 0; i < 4; i++)
#pragma unroll
                for (int j = 0; j < 4; j++)
                    Ps[(4 * ty + i) * PS_STRIDE + tx + 16 * j] = s[i][j];
            __syncthreads();

            // ---- O += P V ----
#pragma unroll 4
            for (int c4 = 0; c4 < 16; c4++) {
                float4 pr[4];
#pragma unroll
                for (int i = 0; i < 4; i++)
                    pr[i] = *(float4*)&Ps[(4 * ty + i) * PS_STRIDE + c4 * 4];
#pragma unroll
                for (int cc = 0; cc < 4; cc++) {
                    float4 vv = *(float4*)&Vs[(c4 * 4 + cc) * HD + tx * 4];
#pragma unroll
                    for (int i = 0; i < 4; i++) {
                        float p = (cc == 0) ? pr[i].x :
                                  (cc == 1) ? pr[i].y :
                                  (cc == 2) ? pr[i].z : pr[i].w;
                        o[i][0] = fmaf(p, vv.x, o[i][0]);
                        o[i][1] = fmaf(p, vv.y, o[i][1]);
                        o[i][2] = fmaf(p, vv.z, o[i][2]);
                        o[i][3] = fmaf(p, vv.w, o[i][3]);
                    }
                }
            }
        }

        // ---- epilogue: normalize and store ----
#pragma unroll
        for (int i = 0; i < 4; i++) {
            const float inv = 1.0f / lrow[i];
            long r = (long)b * SEQ + (long)qi * 64 + 4 * ty + i;
            *(float4*)&out[r * HD + tx * 4] =
                make_float4(o[i][0] * inv, o[i][1] * inv,
                            o[i][2] * inv, o[i][3] * inv);
        }
    }
}

// ---------------------------------------------------------------------------
extern "C" void kernel_launch(void* const* d_in, const int* in_sizes, int n_in,
                              void* d_out, int out_size)
{
    const float* x  = (const float*)d_in[0];
    const float* Wq = (const float*)d_in[1];
    const float* Wk = (const float*)d_in[2];
    const float* Wv = (const float*)d_in[3];
    float* out = (float*)d_out;

    const int attn_smem =
        (64 * QS_STRIDE + 64 * KS_STRIDE + 64 * HD + 64 * PS_STRIDE) * 4;
    cudaFuncSetAttribute(attn, cudaFuncAttributeMaxDynamicSharedMemorySize,
                         attn_smem);

    qkv_proj<<<(BATCH * SEQ) / 64, 256>>>(x, Wq, Wk, Wv);
    attn<<<dim3(32, BATCH), 256, attn_smem>>>(out);
}